// round 13
// baseline (speedup 1.0000x reference)
#include <cuda_runtime.h>
#include <cuda_bf16.h>
#include <cstdint>

#define B_  2
#define C_  512
#define N_  2048
#define H_  8
#define DK_ 64
#define BH_ (B_*H_)

__device__ __nv_bfloat16 g_xthi[B_*N_*C_];
__device__ __nv_bfloat16 g_xtlo[B_*N_*C_];
__device__ __nv_bfloat16 g_whi[3*C_*C_];
__device__ __nv_bfloat16 g_wlo[3*C_*C_];
__device__ __nv_bfloat16 g_qhi[BH_*N_*DK_];
__device__ __nv_bfloat16 g_qlo[BH_*N_*DK_];
__device__ __nv_bfloat16 g_khi[BH_*N_*DK_];
__device__ __nv_bfloat16 g_klo[BH_*N_*DK_];
__device__ float g_v[BH_*N_*DK_];
__device__ float g_o[BH_*N_*DK_];
__device__ __nv_bfloat16 g_vthi[BH_*DK_*N_];
__device__ __nv_bfloat16 g_vtlo[BH_*DK_*N_];
__device__ float g_e[(size_t)BH_*N_*N_];
__device__ float g_tau[BH_*N_];

__device__ __forceinline__ void mma16816(float* d, const uint32_t* a, const uint32_t* b) {
    asm volatile(
        "mma.sync.aligned.m16n8k16.row.col.f32.bf16.bf16.f32 "
        "{%0,%1,%2,%3}, {%4,%5,%6,%7}, {%8,%9}, {%0,%1,%2,%3};"
        : "+f"(d[0]), "+f"(d[1]), "+f"(d[2]), "+f"(d[3])
        : "r"(a[0]), "r"(a[1]), "r"(a[2]), "r"(a[3]), "r"(b[0]), "r"(b[1]));
}
__device__ __forceinline__ void ldsm4(uint32_t* f, uint32_t a) {
    asm volatile("ldmatrix.sync.aligned.m8n8.x4.shared.b16 {%0,%1,%2,%3}, [%4];"
        : "=r"(f[0]), "=r"(f[1]), "=r"(f[2]), "=r"(f[3]) : "r"(a));
}
__device__ __forceinline__ uint32_t smem_u32(const void* p) {
    uint32_t a;
    asm("{ .reg .u64 t; cvta.to.shared.u64 t, %1; cvt.u32.u64 %0, t; }" : "=r"(a) : "l"(p));
    return a;
}
__device__ __forceinline__ void split2(float x, float y, uint32_t& h, uint32_t& l) {
    __nv_bfloat162 hh, ll;
    hh.x = __float2bfloat16(x); ll.x = __float2bfloat16(x - __bfloat162float(hh.x));
    hh.y = __float2bfloat16(y); ll.y = __float2bfloat16(y - __bfloat162float(hh.y));
    h = *(uint32_t*)&hh; l = *(uint32_t*)&ll;
}
__device__ __forceinline__ void cpa16(uint32_t dst, const void* src) {
    asm volatile("cp.async.cg.shared.global [%0], [%1], 16;" :: "r"(dst), "l"(src));
}
#define CPA_COMMIT() asm volatile("cp.async.commit_group;" ::: "memory")
#define CPA_WAIT1()  asm volatile("cp.async.wait_group 1;" ::: "memory")
#define CPA_WAIT0()  asm volatile("cp.async.wait_group 0;" ::: "memory")
#define NBAR(id) asm volatile("bar.sync %0, %1;" :: "r"(id), "r"(64) : "memory")

// ---------------- Kernel 0a: x transpose + split ----------------
__global__ __launch_bounds__(256) void xsplit_kernel(const float* __restrict__ x)
{
    __shared__ float t[64][65];
    const int tid = threadIdx.x;
    const int c0 = blockIdx.x * 64, n0 = blockIdx.y * 64, b = blockIdx.z;
    for (int i = tid; i < 4096; i += 256) {
        int c = i >> 6, n = i & 63;
        t[c][n] = x[(b * C_ + c0 + c) * N_ + n0 + n];
    }
    __syncthreads();
    for (int i = tid; i < 2048; i += 256) {
        int n = i >> 5, c2 = i & 31;
        float v0 = t[c2 * 2][n], v1 = t[c2 * 2 + 1][n];
        uint32_t h, l; split2(v0, v1, h, l);
        size_t o = ((size_t)(b * N_ + n0 + n) * C_ + c0) + c2 * 2;
        *(uint32_t*)(g_xthi + o) = h;
        *(uint32_t*)(g_xtlo + o) = l;
    }
}

// ---------------- Kernel 0b: W split ----------------
__global__ __launch_bounds__(256) void wsplit_kernel(
    const float* __restrict__ Wq, const float* __restrict__ Wk,
    const float* __restrict__ Wv)
{
    const int idx = blockIdx.x * 256 + threadIdx.x;
    const int row = idx >> 7, c4 = idx & 127;
    const int mat = row >> 9, r = row & 511;
    const float* W = (mat == 0) ? Wq : (mat == 1) ? Wk : Wv;
    float4 v = *(const float4*)(W + r * C_ + c4 * 4);
    uint32_t h0, l0, h1, l1;
    split2(v.x, v.y, h0, l0);
    split2(v.z, v.w, h1, l1);
    size_t o = (size_t)row * C_ + c4 * 4;
    *(uint2*)(g_whi + o) = make_uint2(h0, h1);
    *(uint2*)(g_wlo + o) = make_uint2(l0, l1);
}

// ---------------- Kernel 1: QKV, cp.async 2-stage pipeline ----------------
__global__ __launch_bounds__(256, 2) void qkv_kernel(
    const float* __restrict__ bq, const float* __restrict__ bk,
    const float* __restrict__ bv)
{
    extern __shared__ char sm[];
    const int tid = threadIdx.x, w = tid >> 5, lane = tid & 31;
    const int g = lane >> 2, tig = lane & 3;
    const int a_row = (lane & 7) + ((lane >> 3) & 1) * 8;
    const int a_k   = (lane >> 4) * 16;
    const int b_row = (lane & 7) + (lane >> 4) * 8;
    const int b_k   = ((lane >> 3) & 1) * 16;

    const int o0 = blockIdx.x * 128, n0 = blockIdx.y * 128, b = blockIdx.z;
    const int mat = o0 >> 9;
    const float* bias = (mat == 0) ? bq : (mat == 1) ? bk : bv;
    const int wm = (w >> 2) * 64, wn = (w & 3) * 32;
    const uint32_t uS = smem_u32(sm);

    const __nv_bfloat16* ah_g = g_xthi + (size_t)(b * N_ + n0) * C_;
    const __nv_bfloat16* al_g = g_xtlo + (size_t)(b * N_ + n0) * C_;
    const __nv_bfloat16* bh_g = g_whi + (size_t)o0 * C_;
    const __nv_bfloat16* bl_g = g_wlo + (size_t)o0 * C_;

    #pragma unroll
    for (int c = 0; c < 2; c++) {
        const uint32_t st = uS + c * 40960;
        for (int i = tid; i < 512; i += 256) {
            int r = i >> 2, u = i & 3;
            const size_t off = (size_t)r * C_ + c * 32 + u * 8;
            cpa16(st +         r * 80 + u * 16, ah_g + off);
            cpa16(st + 10240 + r * 80 + u * 16, al_g + off);
            cpa16(st + 20480 + r * 80 + u * 16, bh_g + off);
            cpa16(st + 30720 + r * 80 + u * 16, bl_g + off);
        }
        CPA_COMMIT();
    }

    float acc[4][4][4];
    #pragma unroll
    for (int i = 0; i < 4; i++)
        #pragma unroll
        for (int j = 0; j < 4; j++)
            #pragma unroll
            for (int r = 0; r < 4; r++) acc[i][j][r] = 0.f;

    for (int kc = 0; kc < 16; kc++) {
        if (kc + 1 < 16) CPA_WAIT1(); else CPA_WAIT0();
        __syncthreads();

        const uint32_t st = uS + (kc & 1) * 40960;
        const uint32_t uAH = st, uAL = st + 10240, uBH = st + 20480, uBL = st + 30720;

        #pragma unroll
        for (int ks = 0; ks < 2; ks++) {
            const int kb = ks * 32;
            uint32_t ah[4][4], al[4][4], bh4[2][4], bl4[2][4];
            #pragma unroll
            for (int ms = 0; ms < 4; ms++) {
                ldsm4(ah[ms], uAH + (wm + ms * 16 + a_row) * 80 + kb + a_k);
                ldsm4(al[ms], uAL + (wm + ms * 16 + a_row) * 80 + kb + a_k);
            }
            #pragma unroll
            for (int j = 0; j < 2; j++) {
                ldsm4(bh4[j], uBH + (wn + j * 16 + b_row) * 80 + kb + b_k);
                ldsm4(bl4[j], uBL + (wn + j * 16 + b_row) * 80 + kb + b_k);
            }
            #pragma unroll
            for (int ms = 0; ms < 4; ms++)
                #pragma unroll
                for (int ns = 0; ns < 4; ns++) {
                    const uint32_t* bh = &bh4[ns >> 1][(ns & 1) * 2];
                    const uint32_t* bl = &bl4[ns >> 1][(ns & 1) * 2];
                    mma16816(acc[ms][ns], ah[ms], bh);
                    mma16816(acc[ms][ns], ah[ms], bl);
                    mma16816(acc[ms][ns], al[ms], bh);
                }
        }
        __syncthreads();

        if (kc + 2 < 16) {
            const int cn = kc + 2;
            const uint32_t stn = uS + (kc & 1) * 40960;
            for (int i = tid; i < 512; i += 256) {
                int r = i >> 2, u = i & 3;
                const size_t off = (size_t)r * C_ + cn * 32 + u * 8;
                cpa16(stn +         r * 80 + u * 16, ah_g + off);
                cpa16(stn + 10240 + r * 80 + u * 16, al_g + off);
                cpa16(stn + 20480 + r * 80 + u * 16, bh_g + off);
                cpa16(stn + 30720 + r * 80 + u * 16, bl_g + off);
            }
            CPA_COMMIT();
        }
    }

    const int orow0 = o0 & 511;
    #pragma unroll
    for (int ms = 0; ms < 4; ms++)
        #pragma unroll
        for (int ns = 0; ns < 4; ns++) {
            int col = orow0 + wn + ns * 8 + tig * 2;
            int h = col >> 6, d = col & 63;
            float b0 = bias[col], b1 = bias[col + 1];
            int n = n0 + wm + ms * 16 + g;
            size_t i0 = ((size_t)(b * H_ + h) * N_ + n) * DK_ + d;
            size_t i1 = ((size_t)(b * H_ + h) * N_ + n + 8) * DK_ + d;
            float v0 = acc[ms][ns][0] + b0, v1 = acc[ms][ns][1] + b1;
            float v2 = acc[ms][ns][2] + b0, v3 = acc[ms][ns][3] + b1;
            if (mat == 2) {
                *(float2*)(g_v + i0) = make_float2(v0, v1);
                *(float2*)(g_v + i1) = make_float2(v2, v3);
            } else {
                __nv_bfloat16* dh = (mat == 0) ? g_qhi : g_khi;
                __nv_bfloat16* dl = (mat == 0) ? g_qlo : g_klo;
                uint32_t h0, l0, h1, l1;
                split2(v0, v1, h0, l0);
                split2(v2, v3, h1, l1);
                *(uint32_t*)(dh + i0) = h0; *(uint32_t*)(dl + i0) = l0;
                *(uint32_t*)(dh + i1) = h1; *(uint32_t*)(dl + i1) = l1;
            }
        }
}

// ---------------- Kernel 2: E = QK^T/16 + entmax tau. 2 CTAs/SM. ----------------
// 512 thr, warp tile 16x32, K-chunks of 64 keys, 3-stage ring. smem 92160.
__global__ __launch_bounds__(512, 2) void energy_kernel()
{
    extern __shared__ char sm[];
    char* QHI = sm;                 // [128][72bf16] 144B rows = 18432
    char* QLO = sm + 18432;
    char* KB  = sm + 36864;         // 3 x (KHI 9216 + KLO 9216) = 55296

    const int tid = threadIdx.x, w = tid >> 5, lane = tid & 31;
    const int g = lane >> 2, tig = lane & 3;
    const int a_row = (lane & 7) + ((lane >> 3) & 1) * 8;
    const int a_k   = (lane >> 4) * 16;
    const int b_row = (lane & 7) + (lane >> 4) * 8;
    const int b_k   = ((lane >> 3) & 1) * 16;
    const int q0 = blockIdx.x * 128, bh = blockIdx.y;
    const int wm = (w >> 1) * 16, wn = (w & 1) * 32;
    const uint32_t uQH = smem_u32(QHI), uQL = smem_u32(QLO);
    const uint32_t uKB = smem_u32(KB);

    const __nv_bfloat16* qh = g_qhi + ((size_t)bh * N_ + q0) * DK_;
    const __nv_bfloat16* ql = g_qlo + ((size_t)bh * N_ + q0) * DK_;
    for (int i = tid; i < 4096; i += 512) {
        int r = i >> 5, c2 = i & 31;
        *(uint32_t*)(QHI + r * 144 + c2 * 4) = *(const uint32_t*)(qh + r * 64 + c2 * 2);
        *(uint32_t*)(QLO + r * 144 + c2 * 4) = *(const uint32_t*)(ql + r * 64 + c2 * 2);
    }
    const __nv_bfloat16* kh = g_khi + (size_t)bh * N_ * DK_;
    const __nv_bfloat16* kl = g_klo + (size_t)bh * N_ * DK_;
    float* ep = g_e + ((size_t)bh * N_ + q0) * N_;

    #pragma unroll
    for (int c = 0; c < 2; c++) {
        uint32_t kb = uKB + c * 18432;
        int r = tid >> 3, u = tid & 7;
        cpa16(kb + r * 144 + u * 16,        kh + (size_t)(c * 64 + r) * 64 + u * 8);
        cpa16(kb + 9216 + r * 144 + u * 16, kl + (size_t)(c * 64 + r) * 64 + u * 8);
        CPA_COMMIT();
    }
    CPA_WAIT1();
    __syncthreads();

    for (int kc = 0; kc < 32; kc++) {
        if (kc + 2 < 32) {
            uint32_t kbn = uKB + ((kc + 2) % 3) * 18432;
            int r = tid >> 3, u = tid & 7;
            cpa16(kbn + r * 144 + u * 16,
                  kh + (size_t)((kc + 2) * 64 + r) * 64 + u * 8);
            cpa16(kbn + 9216 + r * 144 + u * 16,
                  kl + (size_t)((kc + 2) * 64 + r) * 64 + u * 8);
            CPA_COMMIT();
        }

        const uint32_t uKH = uKB + (kc % 3) * 18432;
        const uint32_t uKL = uKH + 9216;

        float acc[4][4];
        #pragma unroll
        for (int j = 0; j < 4; j++)
            #pragma unroll
            for (int r = 0; r < 4; r++) acc[j][r] = 0.f;

        #pragma unroll
        for (int ks = 0; ks < 4; ks++) {
            const int kb = ks * 32;
            uint32_t ah[4], al[4], bh4[2][4], bl4[2][4];
            ldsm4(ah, uQH + (wm + a_row) * 144 + kb + a_k);
            ldsm4(al, uQL + (wm + a_row) * 144 + kb + a_k);
            #pragma unroll
            for (int j = 0; j < 2; j++) {
                ldsm4(bh4[j], uKH + (wn + j * 16 + b_row) * 144 + kb + b_k);
                ldsm4(bl4[j], uKL + (wn + j * 16 + b_row) * 144 + kb + b_k);
            }
            #pragma unroll
            for (int ns = 0; ns < 4; ns++) {
                const uint32_t* bhp = &bh4[ns >> 1][(ns & 1) * 2];
                const uint32_t* blp = &bl4[ns >> 1][(ns & 1) * 2];
                mma16816(acc[ns], ah, bhp);
                mma16816(acc[ns], ah, blp);
                mma16816(acc[ns], al, bhp);
            }
        }
        const float s = 0.0625f;
        #pragma unroll
        for (int ns = 0; ns < 4; ns++) {
            int row = wm + g;
            int col = kc * 64 + wn + ns * 8 + tig * 2;
            *(float2*)(ep + (size_t)row * N_ + col) =
                make_float2(acc[ns][0] * s, acc[ns][1] * s);
            *(float2*)(ep + (size_t)(row + 8) * N_ + col) =
                make_float2(acc[ns][2] * s, acc[ns][3] * s);
        }

        if (kc + 2 < 32)      CPA_WAIT1();
        else if (kc + 1 < 32) CPA_WAIT0();
        __syncthreads();
    }

    // ---- entmax epilogue: 2 warps per row, z[32]/thread, named-bar reductions ----
    const int pair = w >> 1, half = w & 1;
    const int bid = pair + 1;
    float* red = (float*)(sm + 36864) + pair * 32;   // 32 slots/pair (reuse K ring)

    for (int rr = 0; rr < 16; rr++) {
        const int row = pair * 16 + rr;
        const float* rp = ep + (size_t)row * N_ + half * 1024;
        float z[32];
        #pragma unroll
        for (int b = 0; b < 8; b++) {
            float4 v = *(const float4*)(rp + b * 128 + lane * 4);
            z[4*b] = v.x; z[4*b+1] = v.y; z[4*b+2] = v.z; z[4*b+3] = v.w;
        }
        float m = z[0];
        #pragma unroll
        for (int j = 1; j < 32; j++) m = fmaxf(m, z[j]);
        #pragma unroll
        for (int o = 16; o; o >>= 1) m = fmaxf(m, __shfl_xor_sync(0xffffffffu, m, o));
        if (lane == 0) red[half] = m;
        NBAR(bid);
        m = fmaxf(red[0], red[1]);
        #pragma unroll
        for (int j = 0; j < 32; j++) z[j] -= m;

        float lo = -1.f, hi = 0.f;
        for (int it = 0; it < 6; it++) {
            float mid = 0.5f * (lo + hi), s = 0.f;
            #pragma unroll
            for (int j = 0; j < 32; j++) {
                float t = fmaxf(z[j] - mid, 0.f);
                s = fmaf(t, t, s);
            }
            #pragma unroll
            for (int o = 16; o; o >>= 1) s += __shfl_xor_sync(0xffffffffu, s, o);
            if (lane == 0) red[2 + it * 2 + half] = s;
            NBAR(bid);
            s = red[2 + it * 2] + red[3 + it * 2];
            if (s >= 1.f) lo = mid; else hi = mid;
        }
        // pass 1: {z > lo}
        float c1 = 0.f, c2 = 0.f, cnt = 0.f;
        #pragma unroll
        for (int j = 0; j < 32; j++)
            if (z[j] > lo) { c1 += z[j]; c2 = fmaf(z[j], z[j], c2); cnt += 1.f; }
        #pragma unroll
        for (int o = 16; o; o >>= 1) {
            c1 += __shfl_xor_sync(0xffffffffu, c1, o);
            c2 += __shfl_xor_sync(0xffffffffu, c2, o);
            cnt += __shfl_xor_sync(0xffffffffu, cnt, o);
        }
        if (lane == 0) {
            red[14 + half] = c1; red[16 + half] = c2; red[18 + half] = cnt;
        }
        NBAR(bid);
        c1 = red[14] + red[15]; c2 = red[16] + red[17]; cnt = red[18] + red[19];
        float disc = fmaxf(fmaf(c1, c1, -cnt * (c2 - 1.f)), 0.f);
        float tau = (c1 - sqrtf(disc)) / fmaxf(cnt, 1.f);
        tau = fminf(fmaxf(tau, lo), hi);
        // pass 2: {z > tau}
        c1 = 0.f; c2 = 0.f; cnt = 0.f;
        #pragma unroll
        for (int j = 0; j < 32; j++)
            if (z[j] > tau) { c1 += z[j]; c2 = fmaf(z[j], z[j], c2); cnt += 1.f; }
        #pragma unroll
        for (int o = 16; o; o >>= 1) {
            c1 += __shfl_xor_sync(0xffffffffu, c1, o);
            c2 += __shfl_xor_sync(0xffffffffu, c2, o);
            cnt += __shfl_xor_sync(0xffffffffu, cnt, o);
        }
        if (lane == 0) {
            red[20 + half] = c1; red[22 + half] = c2; red[24 + half] = cnt;
        }
        NBAR(bid);
        c1 = red[20] + red[21]; c2 = red[22] + red[23]; cnt = red[24] + red[25];
        disc = fmaxf(fmaf(c1, c1, -cnt * (c2 - 1.f)), 0.f);
        float tau2 = (c1 - sqrtf(disc)) / fmaxf(cnt, 1.f);
        tau2 = fminf(fmaxf(tau2, -1.f), 0.f);
        if (lane == 0 && half == 0) g_tau[(size_t)bh * N_ + q0 + row] = m + tau2;
        NBAR(bid);   // protect slot reuse next row
    }
}

// ---------------- Kernel 3: V transpose -> bf16 hi/lo [bh][d][k] ----------------
__global__ __launch_bounds__(256) void vt_kernel()
{
    __shared__ float t[64][65];
    const int tid = threadIdx.x, k0 = blockIdx.x * 64, bh = blockIdx.y;
    for (int i = tid; i < 4096; i += 256) {
        int k = i >> 6, d = i & 63;
        t[k][d] = g_v[((size_t)bh * N_ + k0 + k) * DK_ + d];
    }
    __syncthreads();
    for (int i = tid; i < 4096; i += 256) {
        int d = i >> 6, kk = i & 63;
        float v = t[kk][d];
        __nv_bfloat16 h = __float2bfloat16(v);
        __nv_bfloat16 l = __float2bfloat16(v - __bfloat162float(h));
        size_t o = ((size_t)bh * DK_ + d) * N_ + k0 + kk;
        g_vthi[o] = h; g_vtlo[o] = l;
    }
}

// ---------------- Kernel 4: O = P V. 2 CTAs/SM, P single-buf, V 2-stage ----------
// smem: P 36864 | V 2x18432 | taus -> 74240
__global__ __launch_bounds__(512, 2) void pv_kernel()
{
    extern __shared__ char sm[];
    char*  PB    = sm;                        // PH 18432 + PL 18432
    char*  VB    = sm + 36864;                // 2 x (VH 9216 + VL 9216)
    float* staus = (float*)(sm + 73728);      // [128]

    const int tid = threadIdx.x, w = tid >> 5, lane = tid & 31;
    const int g = lane >> 2, tig = lane & 3;
    const int a_row = (lane & 7) + ((lane >> 3) & 1) * 8;
    const int a_k   = (lane >> 4) * 16;
    const int b_row = (lane & 7) + (lane >> 4) * 8;
    const int b_k   = ((lane >> 3) & 1) * 16;
    const int q0 = blockIdx.x * 128, bh = blockIdx.y;
    const int wm = (w >> 1) * 16, wn = (w & 1) * 32;
    const uint32_t uPB = smem_u32(PB), uVB = smem_u32(VB);

    const float* ep = g_e + ((size_t)bh * N_ + q0) * N_;
    const __nv_bfloat16* vh = g_vthi + (size_t)bh * DK_ * N_;
    const __nv_bfloat16* vl = g_vtlo + (size_t)bh * DK_ * N_;

    if (tid < 128) staus[tid] = g_tau[(size_t)bh * N_ + q0 + tid];

    // V prologue: chunk 0 -> slot 0
    {
        int r = tid >> 3, u = tid & 7;
        cpa16(uVB + r * 144 + u * 16,        vh + (size_t)r * N_ + u * 8);
        cpa16(uVB + 9216 + r * 144 + u * 16, vl + (size_t)r * N_ + u * 8);
        CPA_COMMIT();
    }
    __syncthreads();   // staus visible

    float st[8];
    #pragma unroll
    for (int j = 0; j < 8; j++) st[j] = staus[w + 16 * j];

    float acc[4][4];
    #pragma unroll
    for (int j = 0; j < 4; j++)
        #pragma unroll
        for (int r = 0; r < 4; r++) acc[j][r] = 0.f;

    for (int kc = 0; kc < 32; kc++) {
        // issue V[kc+1] into slot (kc+1)&1 (freed: MMA kc-1 closed by trailing sync)
        if (kc + 1 < 32) {
            const uint32_t vb = uVB + ((kc + 1) & 1) * 18432;
            int r = tid >> 3, u = tid & 7;
            cpa16(vb + r * 144 + u * 16,        vh + (size_t)r * N_ + (kc + 1) * 64 + u * 8);
            cpa16(vb + 9216 + r * 144 + u * 16, vl + (size_t)r * N_ + (kc + 1) * 64 + u * 8);
            CPA_COMMIT();
            CPA_WAIT1();   // V[kc] done
        } else {
            CPA_WAIT0();
        }

        // transform E chunk kc -> P (direct gmem read)
        #pragma unroll
        for (int j = 0; j < 8; j++) {
            const int row = w + 16 * j;
            float2 e = *(const float2*)(ep + (size_t)row * N_ + kc * 64 + lane * 2);
            float p0 = fmaxf(e.x - st[j], 0.f); p0 *= p0;
            float p1 = fmaxf(e.y - st[j], 0.f); p1 *= p1;
            uint32_t h, l; split2(p0, p1, h, l);
            *(uint32_t*)(PB +         row * 144 + lane * 4) = h;
            *(uint32_t*)(PB + 18432 + row * 144 + lane * 4) = l;
        }
        __syncthreads();   // P + V[kc] visible to all

        const uint32_t uPH = uPB, uPL = uPB + 18432;
        const uint32_t uVH = uVB + (kc & 1) * 18432;
        const uint32_t uVL = uVH + 9216;
        #pragma unroll
        for (int ks = 0; ks < 4; ks++) {
            const int kb = ks * 32;
            uint32_t ah[4], al[4], bh4[2][4], bl4[2][4];
            ldsm4(ah, uPH + (wm + a_row) * 144 + kb + a_k);
            ldsm4(al, uPL + (wm + a_row) * 144 + kb + a_k);
            #pragma unroll
            for (int j = 0; j < 2; j++) {
                ldsm4(bh4[j], uVH + (wn + j * 16 + b_row) * 144 + kb + b_k);
                ldsm4(bl4[j], uVL + (wn + j * 16 + b_row) * 144 + kb + b_k);
            }
            #pragma unroll
            for (int ns = 0; ns < 4; ns++) {
                const uint32_t* bhp = &bh4[ns >> 1][(ns & 1) * 2];
                const uint32_t* blp = &bl4[ns >> 1][(ns & 1) * 2];
                mma16816(acc[ns], ah, bhp);
                mma16816(acc[ns], ah, blp);
                mma16816(acc[ns], al, bhp);
            }
        }
        __syncthreads();   // MMA done: P writable, V slot (kc+1)&1... kc&1 reusable
    }

    #pragma unroll
    for (int ns = 0; ns < 4; ns++) {
        int row = q0 + wm + g;
        int col = wn + ns * 8 + tig * 2;
        float* p0 = g_o + ((size_t)bh * N_ + row) * DK_ + col;
        float* p1 = g_o + ((size_t)bh * N_ + row + 8) * DK_ + col;
        *(float2*)p0 = make_float2(acc[ns][0], acc[ns][1]);
        *(float2*)p1 = make_float2(acc[ns][2], acc[ns][3]);
    }
}

// ---------------- Kernel 5: residual + LayerNorm ----------------
__global__ __launch_bounds__(128) void ln_kernel(
    const float* __restrict__ x, const float* __restrict__ a2,
    const float* __restrict__ b2, float* __restrict__ out)
{
    const int bn = blockIdx.x, b = bn / N_, n = bn % N_, t = threadIdx.x;
    float v[4];
    #pragma unroll
    for (int i = 0; i < 4; i++) {
        int c = t + 128 * i, h = c >> 6, d = c & 63;
        v[i] = g_o[((size_t)(b * H_ + h) * N_ + n) * DK_ + d];
    }
    float s  = v[0] + v[1] + v[2] + v[3];
    float ss = v[0]*v[0] + v[1]*v[1] + v[2]*v[2] + v[3]*v[3];
    __shared__ float rs[4], rss[4];
    #pragma unroll
    for (int o = 16; o; o >>= 1) {
        s  += __shfl_xor_sync(0xffffffffu, s, o);
        ss += __shfl_xor_sync(0xffffffffu, ss, o);
    }
    int wi = t >> 5, li = t & 31;
    if (li == 0) { rs[wi] = s; rss[wi] = ss; }
    __syncthreads();
    s = rs[0] + rs[1] + rs[2] + rs[3];
    ss = rss[0] + rss[1] + rss[2] + rss[3];
    float mean = s * (1.f / 512.f);
    float var  = fmaxf((ss - 512.f * mean * mean) * (1.f / 511.f), 0.f);
    float inv  = 1.f / (sqrtf(var) + 1e-6f);
    #pragma unroll
    for (int i = 0; i < 4; i++) {
        int c = t + 128 * i;
        out[bn * C_ + c] = a2[c] * (v[i] - mean) * inv + b2[c] + x[(b * C_ + c) * N_ + n];
    }
}

// ---------------------------------------------------------------------------
extern "C" void kernel_launch(void* const* d_in, const int* in_sizes, int n_in,
                              void* d_out, int out_size)
{
    const float* x  = (const float*)d_in[0];
    const float* Wq = (const float*)d_in[1];
    const float* bq = (const float*)d_in[2];
    const float* Wk = (const float*)d_in[3];
    const float* bk = (const float*)d_in[4];
    const float* Wv = (const float*)d_in[5];
    const float* bv = (const float*)d_in[6];
    const float* a2 = (const float*)d_in[7];
    const float* b2 = (const float*)d_in[8];
    float* out = (float*)d_out;

    cudaFuncSetAttribute(qkv_kernel, cudaFuncAttributeMaxDynamicSharedMemorySize, 81920);
    cudaFuncSetAttribute(energy_kernel, cudaFuncAttributeMaxDynamicSharedMemorySize, 92160);
    cudaFuncSetAttribute(pv_kernel, cudaFuncAttributeMaxDynamicSharedMemorySize, 74240);

    xsplit_kernel<<<dim3(8, 32, 2), 256>>>(x);
    wsplit_kernel<<<768, 256>>>(Wq, Wk, Wv);
    qkv_kernel<<<dim3(12, 16, 2), 256, 81920>>>(bq, bk, bv);
    energy_kernel<<<dim3(16, 16), 512, 92160>>>();
    vt_kernel<<<dim3(32, 16), 256>>>();
    pv_kernel<<<dim3(16, 16), 512, 74240>>>();
    ln_kernel<<<B_ * N_, 128>>>(x, a2, b2, out);
}

// round 14
// speedup vs baseline: 1.0385x; 1.0385x over previous
#include <cuda_runtime.h>
#include <cuda_bf16.h>
#include <cstdint>

#define B_  2
#define C_  512
#define N_  2048
#define H_  8
#define DK_ 64
#define BH_ (B_*H_)

__device__ __nv_bfloat16 g_xthi[B_*N_*C_];
__device__ __nv_bfloat16 g_xtlo[B_*N_*C_];
__device__ __nv_bfloat16 g_whi[3*C_*C_];
__device__ __nv_bfloat16 g_wlo[3*C_*C_];
__device__ __nv_bfloat16 g_qhi[BH_*N_*DK_];
__device__ __nv_bfloat16 g_qlo[BH_*N_*DK_];
__device__ __nv_bfloat16 g_khi[BH_*N_*DK_];
__device__ __nv_bfloat16 g_klo[BH_*N_*DK_];
__device__ float g_v[BH_*N_*DK_];
__device__ float g_o[BH_*N_*DK_];
__device__ __nv_bfloat16 g_vthi[BH_*DK_*N_];
__device__ __nv_bfloat16 g_vtlo[BH_*DK_*N_];
__device__ float g_e[(size_t)BH_*N_*N_];
__device__ float g_tau[BH_*N_];

__device__ __forceinline__ void mma16816(float* d, const uint32_t* a, const uint32_t* b) {
    asm volatile(
        "mma.sync.aligned.m16n8k16.row.col.f32.bf16.bf16.f32 "
        "{%0,%1,%2,%3}, {%4,%5,%6,%7}, {%8,%9}, {%0,%1,%2,%3};"
        : "+f"(d[0]), "+f"(d[1]), "+f"(d[2]), "+f"(d[3])
        : "r"(a[0]), "r"(a[1]), "r"(a[2]), "r"(a[3]), "r"(b[0]), "r"(b[1]));
}
__device__ __forceinline__ void ldsm4(uint32_t* f, uint32_t a) {
    asm volatile("ldmatrix.sync.aligned.m8n8.x4.shared.b16 {%0,%1,%2,%3}, [%4];"
        : "=r"(f[0]), "=r"(f[1]), "=r"(f[2]), "=r"(f[3]) : "r"(a));
}
__device__ __forceinline__ uint32_t smem_u32(const void* p) {
    uint32_t a;
    asm("{ .reg .u64 t; cvta.to.shared.u64 t, %1; cvt.u32.u64 %0, t; }" : "=r"(a) : "l"(p));
    return a;
}
__device__ __forceinline__ void split2(float x, float y, uint32_t& h, uint32_t& l) {
    __nv_bfloat162 hh, ll;
    hh.x = __float2bfloat16(x); ll.x = __float2bfloat16(x - __bfloat162float(hh.x));
    hh.y = __float2bfloat16(y); ll.y = __float2bfloat16(y - __bfloat162float(hh.y));
    h = *(uint32_t*)&hh; l = *(uint32_t*)&ll;
}
__device__ __forceinline__ void cpa16(uint32_t dst, const void* src) {
    asm volatile("cp.async.cg.shared.global [%0], [%1], 16;" :: "r"(dst), "l"(src));
}
#define CPA_COMMIT() asm volatile("cp.async.commit_group;" ::: "memory")
#define CPA_WAIT1()  asm volatile("cp.async.wait_group 1;" ::: "memory")
#define CPA_WAIT0()  asm volatile("cp.async.wait_group 0;" ::: "memory")

// ---------------- Kernel 0a: x transpose + split ----------------
__global__ __launch_bounds__(256) void xsplit_kernel(const float* __restrict__ x)
{
    __shared__ float t[64][65];
    const int tid = threadIdx.x;
    const int c0 = blockIdx.x * 64, n0 = blockIdx.y * 64, b = blockIdx.z;
    for (int i = tid; i < 4096; i += 256) {
        int c = i >> 6, n = i & 63;
        t[c][n] = x[(b * C_ + c0 + c) * N_ + n0 + n];
    }
    __syncthreads();
    for (int i = tid; i < 2048; i += 256) {
        int n = i >> 5, c2 = i & 31;
        float v0 = t[c2 * 2][n], v1 = t[c2 * 2 + 1][n];
        uint32_t h, l; split2(v0, v1, h, l);
        size_t o = ((size_t)(b * N_ + n0 + n) * C_ + c0) + c2 * 2;
        *(uint32_t*)(g_xthi + o) = h;
        *(uint32_t*)(g_xtlo + o) = l;
    }
}

// ---------------- Kernel 0b: W split ----------------
__global__ __launch_bounds__(256) void wsplit_kernel(
    const float* __restrict__ Wq, const float* __restrict__ Wk,
    const float* __restrict__ Wv)
{
    const int idx = blockIdx.x * 256 + threadIdx.x;
    const int row = idx >> 7, c4 = idx & 127;
    const int mat = row >> 9, r = row & 511;
    const float* W = (mat == 0) ? Wq : (mat == 1) ? Wk : Wv;
    float4 v = *(const float4*)(W + r * C_ + c4 * 4);
    uint32_t h0, l0, h1, l1;
    split2(v.x, v.y, h0, l0);
    split2(v.z, v.w, h1, l1);
    size_t o = (size_t)row * C_ + c4 * 4;
    *(uint2*)(g_whi + o) = make_uint2(h0, h1);
    *(uint2*)(g_wlo + o) = make_uint2(l0, l1);
}

// ---------------- Kernel 1: QKV, cp.async 2-stage pipeline ----------------
__global__ __launch_bounds__(256, 2) void qkv_kernel(
    const float* __restrict__ bq, const float* __restrict__ bk,
    const float* __restrict__ bv)
{
    extern __shared__ char sm[];
    const int tid = threadIdx.x, w = tid >> 5, lane = tid & 31;
    const int g = lane >> 2, tig = lane & 3;
    const int a_row = (lane & 7) + ((lane >> 3) & 1) * 8;
    const int a_k   = (lane >> 4) * 16;
    const int b_row = (lane & 7) + (lane >> 4) * 8;
    const int b_k   = ((lane >> 3) & 1) * 16;

    const int o0 = blockIdx.x * 128, n0 = blockIdx.y * 128, b = blockIdx.z;
    const int mat = o0 >> 9;
    const float* bias = (mat == 0) ? bq : (mat == 1) ? bk : bv;
    const int wm = (w >> 2) * 64, wn = (w & 3) * 32;
    const uint32_t uS = smem_u32(sm);

    const __nv_bfloat16* ah_g = g_xthi + (size_t)(b * N_ + n0) * C_;
    const __nv_bfloat16* al_g = g_xtlo + (size_t)(b * N_ + n0) * C_;
    const __nv_bfloat16* bh_g = g_whi + (size_t)o0 * C_;
    const __nv_bfloat16* bl_g = g_wlo + (size_t)o0 * C_;

    #pragma unroll
    for (int c = 0; c < 2; c++) {
        const uint32_t st = uS + c * 40960;
        for (int i = tid; i < 512; i += 256) {
            int r = i >> 2, u = i & 3;
            const size_t off = (size_t)r * C_ + c * 32 + u * 8;
            cpa16(st +         r * 80 + u * 16, ah_g + off);
            cpa16(st + 10240 + r * 80 + u * 16, al_g + off);
            cpa16(st + 20480 + r * 80 + u * 16, bh_g + off);
            cpa16(st + 30720 + r * 80 + u * 16, bl_g + off);
        }
        CPA_COMMIT();
    }

    float acc[4][4][4];
    #pragma unroll
    for (int i = 0; i < 4; i++)
        #pragma unroll
        for (int j = 0; j < 4; j++)
            #pragma unroll
            for (int r = 0; r < 4; r++) acc[i][j][r] = 0.f;

    for (int kc = 0; kc < 16; kc++) {
        if (kc + 1 < 16) CPA_WAIT1(); else CPA_WAIT0();
        __syncthreads();

        const uint32_t st = uS + (kc & 1) * 40960;
        const uint32_t uAH = st, uAL = st + 10240, uBH = st + 20480, uBL = st + 30720;

        #pragma unroll
        for (int ks = 0; ks < 2; ks++) {
            const int kb = ks * 32;
            uint32_t ah[4][4], al[4][4], bh4[2][4], bl4[2][4];
            #pragma unroll
            for (int ms = 0; ms < 4; ms++) {
                ldsm4(ah[ms], uAH + (wm + ms * 16 + a_row) * 80 + kb + a_k);
                ldsm4(al[ms], uAL + (wm + ms * 16 + a_row) * 80 + kb + a_k);
            }
            #pragma unroll
            for (int j = 0; j < 2; j++) {
                ldsm4(bh4[j], uBH + (wn + j * 16 + b_row) * 80 + kb + b_k);
                ldsm4(bl4[j], uBL + (wn + j * 16 + b_row) * 80 + kb + b_k);
            }
            #pragma unroll
            for (int ms = 0; ms < 4; ms++)
                #pragma unroll
                for (int ns = 0; ns < 4; ns++) {
                    const uint32_t* bh = &bh4[ns >> 1][(ns & 1) * 2];
                    const uint32_t* bl = &bl4[ns >> 1][(ns & 1) * 2];
                    mma16816(acc[ms][ns], ah[ms], bh);
                    mma16816(acc[ms][ns], ah[ms], bl);
                    mma16816(acc[ms][ns], al[ms], bh);
                }
        }
        __syncthreads();

        if (kc + 2 < 16) {
            const int cn = kc + 2;
            const uint32_t stn = uS + (kc & 1) * 40960;
            for (int i = tid; i < 512; i += 256) {
                int r = i >> 2, u = i & 3;
                const size_t off = (size_t)r * C_ + cn * 32 + u * 8;
                cpa16(stn +         r * 80 + u * 16, ah_g + off);
                cpa16(stn + 10240 + r * 80 + u * 16, al_g + off);
                cpa16(stn + 20480 + r * 80 + u * 16, bh_g + off);
                cpa16(stn + 30720 + r * 80 + u * 16, bl_g + off);
            }
            CPA_COMMIT();
        }
    }

    const int orow0 = o0 & 511;
    #pragma unroll
    for (int ms = 0; ms < 4; ms++)
        #pragma unroll
        for (int ns = 0; ns < 4; ns++) {
            int col = orow0 + wn + ns * 8 + tig * 2;
            int h = col >> 6, d = col & 63;
            float b0 = bias[col], b1 = bias[col + 1];
            int n = n0 + wm + ms * 16 + g;
            size_t i0 = ((size_t)(b * H_ + h) * N_ + n) * DK_ + d;
            size_t i1 = ((size_t)(b * H_ + h) * N_ + n + 8) * DK_ + d;
            float v0 = acc[ms][ns][0] + b0, v1 = acc[ms][ns][1] + b1;
            float v2 = acc[ms][ns][2] + b0, v3 = acc[ms][ns][3] + b1;
            if (mat == 2) {
                *(float2*)(g_v + i0) = make_float2(v0, v1);
                *(float2*)(g_v + i1) = make_float2(v2, v3);
            } else {
                __nv_bfloat16* dh = (mat == 0) ? g_qhi : g_khi;
                __nv_bfloat16* dl = (mat == 0) ? g_qlo : g_klo;
                uint32_t h0, l0, h1, l1;
                split2(v0, v1, h0, l0);
                split2(v2, v3, h1, l1);
                *(uint32_t*)(dh + i0) = h0; *(uint32_t*)(dl + i0) = l0;
                *(uint32_t*)(dh + i1) = h1; *(uint32_t*)(dl + i1) = l1;
            }
        }
}

// ---------------- Kernel 2: E = QK^T/16 (R12 mainloop, no epilogue) ----------------
__global__ __launch_bounds__(512, 1) void energy_kernel()
{
    extern __shared__ char sm[];
    char* QHI = sm;                    // [128][72bf16] (144B rows)
    char* QLO = sm + 18432;
    char* KB  = sm + 36864;            // 3 x (KHI 18432 + KLO 18432)

    const int tid = threadIdx.x, w = tid >> 5, lane = tid & 31;
    const int g = lane >> 2, tig = lane & 3;
    const int a_row = (lane & 7) + ((lane >> 3) & 1) * 8;
    const int a_k   = (lane >> 4) * 16;
    const int b_row = (lane & 7) + (lane >> 4) * 8;
    const int b_k   = ((lane >> 3) & 1) * 16;
    const int q0 = blockIdx.x * 128, bh = blockIdx.y;
    const int wm = (w >> 2) * 32, wn = (w & 3) * 32;
    const uint32_t uQH = smem_u32(QHI), uQL = smem_u32(QLO);
    const uint32_t uKB = smem_u32(KB);

    const __nv_bfloat16* qh = g_qhi + ((size_t)bh * N_ + q0) * DK_;
    const __nv_bfloat16* ql = g_qlo + ((size_t)bh * N_ + q0) * DK_;
    for (int i = tid; i < 4096; i += 512) {
        int r = i >> 5, c2 = i & 31;
        *(uint32_t*)(QHI + r * 144 + c2 * 4) = *(const uint32_t*)(qh + r * 64 + c2 * 2);
        *(uint32_t*)(QLO + r * 144 + c2 * 4) = *(const uint32_t*)(ql + r * 64 + c2 * 2);
    }
    const __nv_bfloat16* kh = g_khi + (size_t)bh * N_ * DK_;
    const __nv_bfloat16* kl = g_klo + (size_t)bh * N_ * DK_;
    float* ep = g_e + ((size_t)bh * N_ + q0) * N_;

    #pragma unroll
    for (int c = 0; c < 2; c++) {
        uint32_t kb = uKB + c * 36864;
        for (int i = tid; i < 1024; i += 512) {
            int r = i >> 3, u = i & 7;
            cpa16(kb + r * 144 + u * 16,         kh + (size_t)(c * 128 + r) * 64 + u * 8);
            cpa16(kb + 18432 + r * 144 + u * 16, kl + (size_t)(c * 128 + r) * 64 + u * 8);
        }
        CPA_COMMIT();
    }
    CPA_WAIT1();
    __syncthreads();

    for (int kc = 0; kc < 16; kc++) {
        if (kc + 2 < 16) {
            uint32_t kbn = uKB + ((kc + 2) % 3) * 36864;
            for (int i = tid; i < 1024; i += 512) {
                int r = i >> 3, u = i & 7;
                cpa16(kbn + r * 144 + u * 16,
                      kh + (size_t)((kc + 2) * 128 + r) * 64 + u * 8);
                cpa16(kbn + 18432 + r * 144 + u * 16,
                      kl + (size_t)((kc + 2) * 128 + r) * 64 + u * 8);
            }
            CPA_COMMIT();
        }

        const uint32_t uKH = uKB + (kc % 3) * 36864;
        const uint32_t uKL = uKH + 18432;

        float acc[2][4][4];
        #pragma unroll
        for (int i = 0; i < 2; i++)
            #pragma unroll
            for (int j = 0; j < 4; j++)
                #pragma unroll
                for (int r = 0; r < 4; r++) acc[i][j][r] = 0.f;

        #pragma unroll
        for (int ks = 0; ks < 4; ks++) {
            const int kb = ks * 32;
            uint32_t ah[2][4], al[2][4], bh4[2][4], bl4[2][4];
            #pragma unroll
            for (int ms = 0; ms < 2; ms++) {
                ldsm4(ah[ms], uQH + (wm + ms * 16 + a_row) * 144 + kb + a_k);
                ldsm4(al[ms], uQL + (wm + ms * 16 + a_row) * 144 + kb + a_k);
            }
            #pragma unroll
            for (int j = 0; j < 2; j++) {
                ldsm4(bh4[j], uKH + (wn + j * 16 + b_row) * 144 + kb + b_k);
                ldsm4(bl4[j], uKL + (wn + j * 16 + b_row) * 144 + kb + b_k);
            }
            #pragma unroll
            for (int ms = 0; ms < 2; ms++)
                #pragma unroll
                for (int ns = 0; ns < 4; ns++) {
                    const uint32_t* bhp = &bh4[ns >> 1][(ns & 1) * 2];
                    const uint32_t* blp = &bl4[ns >> 1][(ns & 1) * 2];
                    mma16816(acc[ms][ns], ah[ms], bhp);
                    mma16816(acc[ms][ns], ah[ms], blp);
                    mma16816(acc[ms][ns], al[ms], bhp);
                }
        }
        const float s = 0.0625f;
        #pragma unroll
        for (int ms = 0; ms < 2; ms++)
            #pragma unroll
            for (int ns = 0; ns < 4; ns++) {
                int row = wm + ms * 16 + g;
                int col = kc * 128 + wn + ns * 8 + tig * 2;
                *(float2*)(ep + (size_t)row * N_ + col) =
                    make_float2(acc[ms][ns][0] * s, acc[ms][ns][1] * s);
                *(float2*)(ep + (size_t)(row + 8) * N_ + col) =
                    make_float2(acc[ms][ns][2] * s, acc[ms][ns][3] * s);
            }

        if (kc + 2 < 16)      CPA_WAIT1();
        else if (kc + 1 < 16) CPA_WAIT0();
        __syncthreads();
    }
}

// ---------------- Kernel 2b: standalone tau (warp-per-row, high occupancy) --------
__global__ __launch_bounds__(256) void tau_kernel()
{
    const int wid = threadIdx.x >> 5, lane = threadIdx.x & 31;
    const size_t row = (size_t)blockIdx.x * 8 + wid;
    const float* rp = g_e + row * N_;

    float z[64];
    #pragma unroll
    for (int b = 0; b < 16; b++) {
        float4 v = *(const float4*)(rp + b * 128 + lane * 4);
        z[4*b] = v.x; z[4*b+1] = v.y; z[4*b+2] = v.z; z[4*b+3] = v.w;
    }
    float m = z[0];
    #pragma unroll
    for (int j = 1; j < 64; j++) m = fmaxf(m, z[j]);
    #pragma unroll
    for (int o = 16; o; o >>= 1) m = fmaxf(m, __shfl_xor_sync(0xffffffffu, m, o));
    #pragma unroll
    for (int j = 0; j < 64; j++) z[j] -= m;

    float lo = -1.f, hi = 0.f;
    for (int it = 0; it < 6; it++) {
        float mid = 0.5f * (lo + hi), s = 0.f;
        #pragma unroll
        for (int j = 0; j < 64; j++) {
            float t = fmaxf(z[j] - mid, 0.f);
            s = fmaf(t, t, s);
        }
        #pragma unroll
        for (int o = 16; o; o >>= 1) s += __shfl_xor_sync(0xffffffffu, s, o);
        if (s >= 1.f) lo = mid; else hi = mid;
    }
    float c1 = 0.f, c2 = 0.f, cnt = 0.f;
    #pragma unroll
    for (int j = 0; j < 64; j++)
        if (z[j] > lo) { c1 += z[j]; c2 = fmaf(z[j], z[j], c2); cnt += 1.f; }
    #pragma unroll
    for (int o = 16; o; o >>= 1) {
        c1 += __shfl_xor_sync(0xffffffffu, c1, o);
        c2 += __shfl_xor_sync(0xffffffffu, c2, o);
        cnt += __shfl_xor_sync(0xffffffffu, cnt, o);
    }
    float disc = fmaxf(fmaf(c1, c1, -cnt * (c2 - 1.f)), 0.f);
    float tau = (c1 - sqrtf(disc)) / fmaxf(cnt, 1.f);
    tau = fminf(fmaxf(tau, lo), hi);
    c1 = 0.f; c2 = 0.f; cnt = 0.f;
    #pragma unroll
    for (int j = 0; j < 64; j++)
        if (z[j] > tau) { c1 += z[j]; c2 = fmaf(z[j], z[j], c2); cnt += 1.f; }
    #pragma unroll
    for (int o = 16; o; o >>= 1) {
        c1 += __shfl_xor_sync(0xffffffffu, c1, o);
        c2 += __shfl_xor_sync(0xffffffffu, c2, o);
        cnt += __shfl_xor_sync(0xffffffffu, cnt, o);
    }
    disc = fmaxf(fmaf(c1, c1, -cnt * (c2 - 1.f)), 0.f);
    float tau2 = (c1 - sqrtf(disc)) / fmaxf(cnt, 1.f);
    tau2 = fminf(fmaxf(tau2, -1.f), 0.f);
    if (lane == 0) g_tau[row] = m + tau2;
}

// ---------------- Kernel 3: V transpose -> bf16 hi/lo [bh][d][k] ----------------
__global__ __launch_bounds__(256) void vt_kernel()
{
    __shared__ float t[64][65];
    const int tid = threadIdx.x, k0 = blockIdx.x * 64, bh = blockIdx.y;
    for (int i = tid; i < 4096; i += 256) {
        int k = i >> 6, d = i & 63;
        t[k][d] = g_v[((size_t)bh * N_ + k0 + k) * DK_ + d];
    }
    __syncthreads();
    for (int i = tid; i < 4096; i += 256) {
        int d = i >> 6, kk = i & 63;
        float v = t[kk][d];
        __nv_bfloat16 h = __float2bfloat16(v);
        __nv_bfloat16 l = __float2bfloat16(v - __bfloat162float(h));
        size_t o = ((size_t)bh * DK_ + d) * N_ + k0 + kk;
        g_vthi[o] = h; g_vtlo[o] = l;
    }
}

// ---------------- Kernel 4: O = P V. 2 CTAs/SM, P single-buf, V 2-stage ----------
__global__ __launch_bounds__(512, 2) void pv_kernel()
{
    extern __shared__ char sm[];
    char*  PB    = sm;                        // PH 18432 + PL 18432
    char*  VB    = sm + 36864;                // 2 x (VH 9216 + VL 9216)
    float* staus = (float*)(sm + 73728);      // [128]

    const int tid = threadIdx.x, w = tid >> 5, lane = tid & 31;
    const int g = lane >> 2, tig = lane & 3;
    const int a_row = (lane & 7) + ((lane >> 3) & 1) * 8;
    const int a_k   = (lane >> 4) * 16;
    const int b_row = (lane & 7) + (lane >> 4) * 8;
    const int b_k   = ((lane >> 3) & 1) * 16;
    const int q0 = blockIdx.x * 128, bh = blockIdx.y;
    const int wm = (w >> 1) * 16, wn = (w & 1) * 32;
    const uint32_t uPB = smem_u32(PB), uVB = smem_u32(VB);

    const float* ep = g_e + ((size_t)bh * N_ + q0) * N_;
    const __nv_bfloat16* vh = g_vthi + (size_t)bh * DK_ * N_;
    const __nv_bfloat16* vl = g_vtlo + (size_t)bh * DK_ * N_;

    if (tid < 128) staus[tid] = g_tau[(size_t)bh * N_ + q0 + tid];

    {
        int r = tid >> 3, u = tid & 7;
        cpa16(uVB + r * 144 + u * 16,        vh + (size_t)r * N_ + u * 8);
        cpa16(uVB + 9216 + r * 144 + u * 16, vl + (size_t)r * N_ + u * 8);
        CPA_COMMIT();
    }
    __syncthreads();

    float st[8];
    #pragma unroll
    for (int j = 0; j < 8; j++) st[j] = staus[w + 16 * j];

    float acc[4][4];
    #pragma unroll
    for (int j = 0; j < 4; j++)
        #pragma unroll
        for (int r = 0; r < 4; r++) acc[j][r] = 0.f;

    for (int kc = 0; kc < 32; kc++) {
        if (kc + 1 < 32) {
            const uint32_t vb = uVB + ((kc + 1) & 1) * 18432;
            int r = tid >> 3, u = tid & 7;
            cpa16(vb + r * 144 + u * 16,        vh + (size_t)r * N_ + (kc + 1) * 64 + u * 8);
            cpa16(vb + 9216 + r * 144 + u * 16, vl + (size_t)r * N_ + (kc + 1) * 64 + u * 8);
            CPA_COMMIT();
            CPA_WAIT1();
        } else {
            CPA_WAIT0();
        }

        #pragma unroll
        for (int j = 0; j < 8; j++) {
            const int row = w + 16 * j;
            float2 e = *(const float2*)(ep + (size_t)row * N_ + kc * 64 + lane * 2);
            float p0 = fmaxf(e.x - st[j], 0.f); p0 *= p0;
            float p1 = fmaxf(e.y - st[j], 0.f); p1 *= p1;
            uint32_t h, l; split2(p0, p1, h, l);
            *(uint32_t*)(PB +         row * 144 + lane * 4) = h;
            *(uint32_t*)(PB + 18432 + row * 144 + lane * 4) = l;
        }
        __syncthreads();

        const uint32_t uPH = uPB, uPL = uPB + 18432;
        const uint32_t uVH = uVB + (kc & 1) * 18432;
        const uint32_t uVL = uVH + 9216;
        #pragma unroll
        for (int ks = 0; ks < 4; ks++) {
            const int kb = ks * 32;
            uint32_t ah[4], al[4], bh4[2][4], bl4[2][4];
            ldsm4(ah, uPH + (wm + a_row) * 144 + kb + a_k);
            ldsm4(al, uPL + (wm + a_row) * 144 + kb + a_k);
            #pragma unroll
            for (int j = 0; j < 2; j++) {
                ldsm4(bh4[j], uVH + (wn + j * 16 + b_row) * 144 + kb + b_k);
                ldsm4(bl4[j], uVL + (wn + j * 16 + b_row) * 144 + kb + b_k);
            }
            #pragma unroll
            for (int ns = 0; ns < 4; ns++) {
                const uint32_t* bhp = &bh4[ns >> 1][(ns & 1) * 2];
                const uint32_t* blp = &bl4[ns >> 1][(ns & 1) * 2];
                mma16816(acc[ns], ah, bhp);
                mma16816(acc[ns], ah, blp);
                mma16816(acc[ns], al, bhp);
            }
        }
        __syncthreads();
    }

    #pragma unroll
    for (int ns = 0; ns < 4; ns++) {
        int row = q0 + wm + g;
        int col = wn + ns * 8 + tig * 2;
        float* p0 = g_o + ((size_t)bh * N_ + row) * DK_ + col;
        float* p1 = g_o + ((size_t)bh * N_ + row + 8) * DK_ + col;
        *(float2*)p0 = make_float2(acc[ns][0], acc[ns][1]);
        *(float2*)p1 = make_float2(acc[ns][2], acc[ns][3]);
    }
}

// ---------------- Kernel 5: residual + LayerNorm ----------------
__global__ __launch_bounds__(128) void ln_kernel(
    const float* __restrict__ x, const float* __restrict__ a2,
    const float* __restrict__ b2, float* __restrict__ out)
{
    const int bn = blockIdx.x, b = bn / N_, n = bn % N_, t = threadIdx.x;
    float v[4];
    #pragma unroll
    for (int i = 0; i < 4; i++) {
        int c = t + 128 * i, h = c >> 6, d = c & 63;
        v[i] = g_o[((size_t)(b * H_ + h) * N_ + n) * DK_ + d];
    }
    float s  = v[0] + v[1] + v[2] + v[3];
    float ss = v[0]*v[0] + v[1]*v[1] + v[2]*v[2] + v[3]*v[3];
    __shared__ float rs[4], rss[4];
    #pragma unroll
    for (int o = 16; o; o >>= 1) {
        s  += __shfl_xor_sync(0xffffffffu, s, o);
        ss += __shfl_xor_sync(0xffffffffu, ss, o);
    }
    int wi = t >> 5, li = t & 31;
    if (li == 0) { rs[wi] = s; rss[wi] = ss; }
    __syncthreads();
    s = rs[0] + rs[1] + rs[2] + rs[3];
    ss = rss[0] + rss[1] + rss[2] + rss[3];
    float mean = s * (1.f / 512.f);
    float var  = fmaxf((ss - 512.f * mean * mean) * (1.f / 511.f), 0.f);
    float inv  = 1.f / (sqrtf(var) + 1e-6f);
    #pragma unroll
    for (int i = 0; i < 4; i++) {
        int c = t + 128 * i;
        out[bn * C_ + c] = a2[c] * (v[i] - mean) * inv + b2[c] + x[(b * C_ + c) * N_ + n];
    }
}

// ---------------------------------------------------------------------------
extern "C" void kernel_launch(void* const* d_in, const int* in_sizes, int n_in,
                              void* d_out, int out_size)
{
    const float* x  = (const float*)d_in[0];
    const float* Wq = (const float*)d_in[1];
    const float* bq = (const float*)d_in[2];
    const float* Wk = (const float*)d_in[3];
    const float* bk = (const float*)d_in[4];
    const float* Wv = (const float*)d_in[5];
    const float* bv = (const float*)d_in[6];
    const float* a2 = (const float*)d_in[7];
    const float* b2 = (const float*)d_in[8];
    float* out = (float*)d_out;

    cudaFuncSetAttribute(qkv_kernel, cudaFuncAttributeMaxDynamicSharedMemorySize, 81920);
    cudaFuncSetAttribute(energy_kernel, cudaFuncAttributeMaxDynamicSharedMemorySize, 147456);
    cudaFuncSetAttribute(pv_kernel, cudaFuncAttributeMaxDynamicSharedMemorySize, 74240);

    xsplit_kernel<<<dim3(8, 32, 2), 256>>>(x);
    wsplit_kernel<<<768, 256>>>(Wq, Wk, Wv);
    qkv_kernel<<<dim3(12, 16, 2), 256, 81920>>>(bq, bk, bv);
    energy_kernel<<<dim3(16, 16), 512, 147456>>>();
    tau_kernel<<<BH_ * N_ / 8, 256>>>();
    vt_kernel<<<dim3(32, 16), 256>>>();
    pv_kernel<<<dim3(16, 16), 512, 74240>>>();
    ln_kernel<<<B_ * N_, 128>>>(x, a2, b2, out);
}